// round 9
// baseline (speedup 1.0000x reference)
#include <cuda_runtime.h>
#include <cuda_fp16.h>
#include <float.h>
#include <math.h>
#include <stdint.h>

// Problem constants
#define BSZ   2
#define NN    1024
#define EE    2048
#define LTOT  3072
#define HEADS 8
#define DHEAD 64
#define INNER 512
#define SCALE 0.125f
#define LOG2E 1.4426950408889634f
#define NCH   16                                // vmean chunks per (b,h)

// Scratch (fp16 intermediates)
__device__ __half g_qh[BSZ * HEADS * LTOT * DHEAD];   // pre-scaled by SCALE*LOG2E
__device__ __half g_kh[BSZ * HEADS * LTOT * DHEAD];
__device__ __half g_vh[BSZ * HEADS * LTOT * DHEAD];
__device__ __half g_oh[BSZ * LTOT * INNER];
__device__ int    g_mask[BSZ * LTOT];
__device__ int    g_kidx[BSZ * LTOT];                 // compacted unmasked indices
__device__ int    g_nk[BSZ];
__device__ float  g_vpart[BSZ * HEADS * NCH * DHEAD]; // partial V sums

// ---------------------------------------------------------------------------
// PTX helpers
// ---------------------------------------------------------------------------
__device__ __forceinline__ uint32_t sptr(const void* p) {
    return (uint32_t)__cvta_generic_to_shared(p);
}
__device__ __forceinline__ void ldsm_x4(uint32_t& r0, uint32_t& r1,
                                        uint32_t& r2, uint32_t& r3, uint32_t addr) {
    asm volatile("ldmatrix.sync.aligned.m8n8.x4.shared.b16 {%0,%1,%2,%3}, [%4];"
                 : "=r"(r0), "=r"(r1), "=r"(r2), "=r"(r3) : "r"(addr));
}
__device__ __forceinline__ void ldsm_x4_t(uint32_t& r0, uint32_t& r1,
                                          uint32_t& r2, uint32_t& r3, uint32_t addr) {
    asm volatile("ldmatrix.sync.aligned.m8n8.x4.trans.shared.b16 {%0,%1,%2,%3}, [%4];"
                 : "=r"(r0), "=r"(r1), "=r"(r2), "=r"(r3) : "r"(addr));
}
__device__ __forceinline__ void mma_f16(float c[4],
                                        uint32_t a0, uint32_t a1, uint32_t a2, uint32_t a3,
                                        uint32_t b0, uint32_t b1) {
    asm volatile(
        "mma.sync.aligned.m16n8k16.row.col.f32.f16.f16.f32 "
        "{%0,%1,%2,%3}, {%4,%5,%6,%7}, {%8,%9}, {%0,%1,%2,%3};"
        : "+f"(c[0]), "+f"(c[1]), "+f"(c[2]), "+f"(c[3])
        : "r"(a0), "r"(a1), "r"(a2), "r"(a3), "r"(b0), "r"(b1));
}
__device__ __forceinline__ void cp16(uint32_t dst, const void* src) {
    asm volatile("cp.async.cg.shared.global [%0], [%1], 16;" :: "r"(dst), "l"(src));
}
__device__ __forceinline__ void cp_commit() {
    asm volatile("cp.async.commit_group;");
}
__device__ __forceinline__ void cp_wait0() {
    asm volatile("cp.async.wait_group 0;");
}
__device__ __forceinline__ uint32_t packh2(float x, float y) {
    __half2 h = __floats2half2_rn(x, y);
    return *reinterpret_cast<uint32_t*>(&h);
}
__device__ __forceinline__ float fexp2(float x) {
    float y;
    asm("ex2.approx.ftz.f32 %0, %1;" : "=f"(y) : "f"(x));
    return y;
}

// ---------------------------------------------------------------------------
// Mask decode + per-batch compaction of unmasked indices.
// ---------------------------------------------------------------------------
__global__ void mask_kernel(const unsigned char* __restrict__ raw) {
    __shared__ int partial[256];
    __shared__ int pfx[256];
    const int n = BSZ * LTOT;
    const int b = blockIdx.x;
    const int tid = threadIdx.x;

    int cnt = 0;
    for (int i = tid; i < n; i += 256) cnt += (raw[i] != 0);
    partial[tid] = cnt;
    __syncthreads();
    for (int s = 128; s > 0; s >>= 1) {
        if (tid < s) partial[tid] += partial[tid + s];
        __syncthreads();
    }
    const int width1 = partial[0] > (n * 3 / 8);
    const int* raw32 = (const int*)raw;

    int bits[12];
    int myc = 0;
    #pragma unroll
    for (int i = 0; i < 12; i++) {
        int li = tid * 12 + i;
        int gi = b * LTOT + li;
        int v = width1 ? (raw[gi] != 0) : (raw32[gi] != 0);
        g_mask[gi] = v;
        bits[i] = v;
        myc += v;
    }
    pfx[tid] = myc;
    __syncthreads();
    if (tid == 0) {
        int acc = 0;
        for (int t = 0; t < 256; t++) { int c = pfx[t]; pfx[t] = acc; acc += c; }
        g_nk[b] = acc;
    }
    __syncthreads();
    int off = b * LTOT + pfx[tid];
    #pragma unroll
    for (int i = 0; i < 12; i++)
        if (bits[i]) g_kidx[off++] = tid * 12 + i;
}

// ---------------------------------------------------------------------------
// Partial V sums: grid = BSZ*HEADS*NCH (chunks of LTOT/NCH = 192 rows).
// ---------------------------------------------------------------------------
__global__ void vmean_kernel() {
    const int bh = blockIdx.x / NCH;
    const int chunk = blockIdx.x % NCH;
    const int CROWS = LTOT / NCH;                // 192
    const __half* Vg = g_vh + (size_t)bh * LTOT * DHEAD + (size_t)chunk * CROWS * DHEAD;
    const int tid = threadIdx.x;
    const int rg = tid >> 3;           // 0..31 row group
    const int dg = tid & 7;            // covers d = dg*8 .. dg*8+7

    float acc[8] = {};
    for (int r = rg; r < CROWS; r += 32) {
        uint4 u = *(const uint4*)(Vg + (size_t)r * DHEAD + dg * 8);
        const __half2* h2 = (const __half2*)&u;
        #pragma unroll
        for (int j = 0; j < 4; j++) {
            float2 f = __half22float2(h2[j]);
            acc[2 * j]     += f.x;
            acc[2 * j + 1] += f.y;
        }
    }

    __shared__ float sm[256][8];
    #pragma unroll
    for (int j = 0; j < 8; j++) sm[tid][j] = acc[j];
    __syncthreads();

    if (tid < DHEAD) {
        int d = tid;
        int srcdg = d >> 3, j = d & 7;
        float s = 0.f;
        #pragma unroll
        for (int r = 0; r < 32; r++) s += sm[srcdg + 8 * r][j];
        g_vpart[(bh * NCH + chunk) * DHEAD + d] = s;
    }
}

// ---------------------------------------------------------------------------
// GEMM body (device fn): C = (A' @ W + bias) * scale, 128x64 tile, BK=32,
// 256 threads = 8 warps (4x2), warp tile 32x32. AHALF: A fp16 else fp32.
// DSTMODE 0: scatter fp16 into [B,H,L,D]; 1: fp32 [m, Ncols].
// ---------------------------------------------------------------------------
template <bool AHALF, int DSTMODE>
__device__ __forceinline__ void gemm_body(
        const void* __restrict__ Ap, const float* __restrict__ W,
        const float* __restrict__ bias, void* __restrict__ dst, float scl,
        int K, int Ncols, int rowsPerBatch, int aBatchStride, int aSeqOff,
        int dstSeqOff, int row0, int col0) {
    __shared__ __align__(16) __half sA[128 * 40];
    __shared__ __align__(16) __half sW[32 * 72];

    const int tid = threadIdx.x;
    const int warp = tid >> 5, lane = tid & 31;
    const int g = lane >> 2, qd = lane & 3;
    const int wy = warp >> 1, wx = warp & 1;

    const uint32_t uA = sptr(sA);
    const uint32_t uW = sptr(sW);
    const int offA = ((lane & 7) + ((lane >> 3) & 1) * 8) * 80 + (lane >> 4) * 16;
    const int offW = ((lane & 7) + ((lane >> 3) & 1) * 8) * 144 + (lane >> 4) * 16;

    float acc[2][4][4] = {};

    for (int kt = 0; kt < K; kt += 32) {
        #pragma unroll
        for (int t = 0; t < 8; t++) {
            int idx = tid + t * 256;
            int i = idx >> 4, k2 = idx & 15;
            int m = row0 + i;
            int bb = m / rowsPerBatch;
            int r = m - bb * rowsPerBatch;
            size_t arow = (size_t)(bb * aBatchStride + aSeqOff + r) * K + kt + 2 * k2;
            if (AHALF) {
                ((__half2*)sA)[i * 20 + k2] = *(const __half2*)((const __half*)Ap + arow);
            } else {
                float2 v = *(const float2*)((const float*)Ap + arow);
                ((__half2*)sA)[i * 20 + k2] = __floats2half2_rn(v.x, v.y);
            }
        }
        #pragma unroll
        for (int t = 0; t < 4; t++) {
            int idx = tid + t * 256;
            int kr = idx >> 5, n2 = idx & 31;
            float2 v = *(const float2*)&W[(size_t)(kt + kr) * Ncols + col0 + 2 * n2];
            ((__half2*)sW)[kr * 36 + n2] = __floats2half2_rn(v.x, v.y);
        }
        __syncthreads();

        #pragma unroll
        for (int kk = 0; kk < 2; kk++) {
            uint32_t a[2][4];
            #pragma unroll
            for (int mt = 0; mt < 2; mt++)
                ldsm_x4(a[mt][0], a[mt][1], a[mt][2], a[mt][3],
                        uA + (wy * 32 + mt * 16) * 80 + kk * 32 + offA);
            #pragma unroll
            for (int p = 0; p < 2; p++) {
                uint32_t b0, b1, b2, b3;
                ldsm_x4_t(b0, b1, b2, b3,
                          uW + kk * 16 * 144 + (wx * 32 + p * 16) * 2 + offW);
                mma_f16(acc[0][2 * p],     a[0][0], a[0][1], a[0][2], a[0][3], b0, b1);
                mma_f16(acc[0][2 * p + 1], a[0][0], a[0][1], a[0][2], a[0][3], b2, b3);
                mma_f16(acc[1][2 * p],     a[1][0], a[1][1], a[1][2], a[1][3], b0, b1);
                mma_f16(acc[1][2 * p + 1], a[1][0], a[1][1], a[1][2], a[1][3], b2, b3);
            }
        }
        __syncthreads();
    }

    #pragma unroll
    for (int mt = 0; mt < 2; mt++) {
        #pragma unroll
        for (int hh = 0; hh < 2; hh++) {
            int m = row0 + wy * 32 + mt * 16 + g + 8 * hh;
            int bb = m / rowsPerBatch;
            int r = m - bb * rowsPerBatch;
            #pragma unroll
            for (int n = 0; n < 4; n++) {
                int c = col0 + wx * 32 + n * 8 + 2 * qd;
                float v0 = (acc[mt][n][hh * 2 + 0] + bias[c]) * scl;
                float v1 = (acc[mt][n][hh * 2 + 1] + bias[c + 1]) * scl;
                if (DSTMODE == 0) {
                    int hidx = c >> 6, d = c & 63;
                    __half* dh = (__half*)dst;
                    *(__half2*)&dh[((size_t)(bb * HEADS + hidx) * LTOT +
                                    dstSeqOff + r) * DHEAD + d] = __floats2half2_rn(v0, v1);
                } else {
                    float* df = (float*)dst;
                    *(float2*)&df[(size_t)m * Ncols + c] = make_float2(v0, v1);
                }
            }
        }
    }
}

// ---------------------------------------------------------------------------
// Fused QKV projections (node + edge, all six GEMMs) in one launch.
// ---------------------------------------------------------------------------
__global__ __launch_bounds__(256) void qkv_kernel(
        const float* __restrict__ nodes, const float* __restrict__ edges,
        const float* Wq, const float* Wk, const float* Wv,
        const float* bq, const float* bk, const float* bv,
        const float* Weq, const float* Wek, const float* Wev,
        const float* beq, const float* bek, const float* bev,
        __half* qp, __half* kp, __half* vp, float qscale) {
    const int t = blockIdx.x;
    if (t < 384) {
        const int z = t / 128, r = t % 128;
        const int col0 = (r & 7) * 64, row0 = (r >> 3) * 128;
        const float* W    = (z == 0) ? Wq : (z == 1) ? Wk : Wv;
        const float* bias = (z == 0) ? bq : (z == 1) ? bk : bv;
        __half* dst       = (z == 0) ? qp : (z == 1) ? kp : vp;
        const float scl   = (z == 0) ? qscale : 1.f;
        gemm_body<false, 0>(nodes, W, bias, dst, scl,
                            128, 512, 1024, 1024, 0, 0, row0, col0);
    } else {
        const int u = t - 384;
        const int z = u / 256, r = u % 256;
        const int col0 = (r & 7) * 64, row0 = (r >> 3) * 128;
        const float* W    = (z == 0) ? Weq : (z == 1) ? Wek : Wev;
        const float* bias = (z == 0) ? beq : (z == 1) ? bek : bev;
        __half* dst       = (z == 0) ? qp : (z == 1) ? kp : vp;
        const float scl   = (z == 0) ? qscale : 1.f;
        gemm_body<false, 0>(edges, W, bias, dst, scl,
                            256, 512, 2048, 2048, 0, 1024, row0, col0);
    }
}

// ---------------------------------------------------------------------------
// Fused output projections (node + edge) in one launch. 160 CTAs.
// ---------------------------------------------------------------------------
__global__ __launch_bounds__(256) void outproj_kernel(
        const float* __restrict__ Wo, const float* __restrict__ bo,
        const float* __restrict__ Weo, const float* __restrict__ beo,
        float* __restrict__ out) {
    const int t = blockIdx.x;
    if (t < 32) {
        const int col0 = (t & 1) * 64, row0 = (t >> 1) * 128;
        gemm_body<true, 1>(g_oh, Wo, bo, out, 1.f,
                           512, 128, 1024, 3072, 0, 0, row0, col0);
    } else {
        const int u = t - 32;
        const int col0 = (u & 3) * 64, row0 = (u >> 2) * 128;
        gemm_body<true, 1>(g_oh, Weo, beo, out + 2 * 1024 * 128, 1.f,
                           512, 256, 2048, 3072, 1024, 0, row0, col0);
    }
}

// ---------------------------------------------------------------------------
// Flash attention, Br=64 (128 threads, 4 warps) over compacted rows
// (queries AND keys). Finer CTA granularity doubles schedulable units
// (~384 active CTAs) to hide mma/softmax latency. Idle CTAs (q0 >= nk)
// patch masked rows of g_oh with the uniform-softmax result.
// ---------------------------------------------------------------------------
#define KVSTR 72
#define KVBUF_H (64 * KVSTR)
#define KVBUF_B (KVBUF_H * 2)
#define ATTN_SMEM_BYTES (4 * KVBUF_B)
#define QTILES 48                                // LTOT/64

__device__ __forceinline__ void patch_tiles(int b, int h, int bh, int pstart, int pstep) {
    __shared__ float vms[64];
    const int tid = threadIdx.x;
    if (tid < 64) {
        float s = 0.f;
        #pragma unroll
        for (int c = 0; c < NCH; c++) s += g_vpart[(bh * NCH + c) * DHEAD + tid];
        vms[tid] = s * (1.0f / LTOT);
    }
    __syncthreads();
    const int dg = tid & 7;
    uint4 hv;
    hv.x = packh2(vms[dg * 8 + 0], vms[dg * 8 + 1]);
    hv.y = packh2(vms[dg * 8 + 2], vms[dg * 8 + 3]);
    hv.z = packh2(vms[dg * 8 + 4], vms[dg * 8 + 5]);
    hv.w = packh2(vms[dg * 8 + 6], vms[dg * 8 + 7]);
    for (int p = pstart; p < QTILES; p += pstep) {
        #pragma unroll
        for (int pass = 0; pass < 4; pass++) {
            int r = p * 64 + pass * 16 + (tid >> 3);
            if (!g_mask[b * LTOT + r])
                *(uint4*)&g_oh[(size_t)(b * LTOT + r) * INNER + h * DHEAD + dg * 8] = hv;
        }
    }
}

__global__ __launch_bounds__(128, 4) void attn_f16_kernel() {
    const int bh = blockIdx.y;
    const int b = bh >> 3, h = bh & 7;
    const int nk = g_nk[b];
    const int q0 = blockIdx.x * 64;
    const int qtiles = (nk + 63) >> 6;
    const int nidle = QTILES - qtiles;

    if (q0 >= nk) {
        patch_tiles(b, h, bh, blockIdx.x - qtiles, nidle);
        return;
    }

    extern __shared__ __align__(16) char smraw[];
    __half* Kh = (__half*)smraw;                 // [2][64][72]
    __half* Vh = (__half*)(smraw + 2 * KVBUF_B); // [2][64][72]

    const int tid = threadIdx.x;
    const int warp = tid >> 5, lane = tid & 31;
    const int g = lane >> 2, qd = lane & 3;

    const __half* Qg = g_qh + (size_t)bh * LTOT * DHEAD;
    const __half* Kg = g_kh + (size_t)bh * LTOT * DHEAD;
    const __half* Vg = g_vh + (size_t)bh * LTOT * DHEAD;
    const int* kidx = g_kidx + b * LTOT;
    const int NIT = (nk + 63) >> 6;

    const uint32_t uK = sptr(Kh), uV = sptr(Vh);
    const int offA = ((lane & 7) + ((lane >> 3) & 1) * 8) * 144 + (lane >> 4) * 16;
    const int offK = ((lane & 7) + ((lane >> 4) & 1) * 8) * 144 + ((lane >> 3) & 1) * 16;

    const int prow = tid >> 3;                   // 0..15
    const int pch = (tid & 7) * 16;              // byte offset 0..112

    // Prologue: gather-load tile 0 (64 rows x 8 chunks, 128 threads x 4 passes)
    {
        #pragma unroll
        for (int rr = 0; rr < 4; rr++) {
            int r = prow + rr * 16;
            int idx = (r < nk) ? kidx[r] : 0;
            cp16(uK + r * 144 + pch, Kg + (size_t)idx * 64 + (pch >> 1));
            cp16(uV + r * 144 + pch, Vg + (size_t)idx * 64 + (pch >> 1));
        }
        cp_commit();
    }

    // Query rows (gathered)
    const int qr_a = q0 + warp * 16 + g;
    const int qr_b = qr_a + 8;
    const int valid0 = qr_a < nk;
    const int valid1 = qr_b < nk;
    const int qi0 = valid0 ? kidx[qr_a] : kidx[0];
    const int qi1 = valid1 ? kidx[qr_b] : kidx[0];

    uint32_t qa[4][4];
    {
        const __half* qr0p = Qg + (size_t)qi0 * DHEAD;
        const __half* qr1p = Qg + (size_t)qi1 * DHEAD;
        #pragma unroll
        for (int kk = 0; kk < 4; kk++) {
            int c = kk * 16 + 2 * qd;
            qa[kk][0] = *(const uint32_t*)(qr0p + c);
            qa[kk][1] = *(const uint32_t*)(qr1p + c);
            qa[kk][2] = *(const uint32_t*)(qr0p + c + 8);
            qa[kk][3] = *(const uint32_t*)(qr1p + c + 8);
        }
    }

    float m_i[2] = {-FLT_MAX, -FLT_MAX};
    float l_i[2] = {0.f, 0.f};
    float o[8][4] = {};

    for (int it = 0; it < NIT; it++) {
        const int bf = it & 1;
        const int k0 = it * 64;
        cp_wait0();
        __syncthreads();

        if (it + 1 < NIT) {
            uint32_t uKn = uK + (bf ^ 1) * KVBUF_B;
            uint32_t uVn = uV + (bf ^ 1) * KVBUF_B;
            #pragma unroll
            for (int rr = 0; rr < 4; rr++) {
                int r = prow + rr * 16;
                int gi = k0 + 64 + r;
                int idx = (gi < nk) ? kidx[gi] : 0;
                cp16(uKn + r * 144 + pch, Kg + (size_t)idx * 64 + (pch >> 1));
                cp16(uVn + r * 144 + pch, Vg + (size_t)idx * 64 + (pch >> 1));
            }
            cp_commit();
        }

        const uint32_t uKb = uK + bf * KVBUF_B;
        const uint32_t uVb = uV + bf * KVBUF_B;

        // ---- S = Q @ K^T ----
        float s[8][4] = {};
        #pragma unroll
        for (int kk = 0; kk < 4; kk++) {
            #pragma unroll
            for (int p = 0; p < 4; p++) {
                uint32_t b0, b1, b2, b3;
                ldsm_x4(b0, b1, b2, b3, uKb + p * 16 * 144 + kk * 32 + offK);
                mma_f16(s[2 * p],     qa[kk][0], qa[kk][1], qa[kk][2], qa[kk][3], b0, b1);
                mma_f16(s[2 * p + 1], qa[kk][0], qa[kk][1], qa[kk][2], qa[kk][3], b2, b3);
            }
        }

        // ---- tail masking (key side) ----
        if (k0 + 64 > nk) {
            #pragma unroll
            for (int nt = 0; nt < 8; nt++) {
                int j0 = k0 + nt * 8 + 2 * qd;
                if (j0 >= nk)     { s[nt][0] = -FLT_MAX; s[nt][2] = -FLT_MAX; }
                if (j0 + 1 >= nk) { s[nt][1] = -FLT_MAX; s[nt][3] = -FLT_MAX; }
            }
        }

        // ---- online softmax (base-2) ----
        #pragma unroll
        for (int hh = 0; hh < 2; hh++) {
            float mx = -FLT_MAX;
            #pragma unroll
            for (int nt = 0; nt < 8; nt++)
                mx = fmaxf(mx, fmaxf(s[nt][hh * 2], s[nt][hh * 2 + 1]));
            mx = fmaxf(mx, __shfl_xor_sync(0xffffffffu, mx, 1));
            mx = fmaxf(mx, __shfl_xor_sync(0xffffffffu, mx, 2));
            float mnew = fmaxf(m_i[hh], mx);
            float corr = fexp2(m_i[hh] - mnew);
            m_i[hh] = mnew;
            float rs = 0.f;
            #pragma unroll
            for (int nt = 0; nt < 8; nt++) {
                float p0 = fexp2(s[nt][hh * 2]     - mnew);
                float p1 = fexp2(s[nt][hh * 2 + 1] - mnew);
                rs += p0 + p1;
                s[nt][hh * 2]     = p0;
                s[nt][hh * 2 + 1] = p1;
            }
            rs += __shfl_xor_sync(0xffffffffu, rs, 1);
            rs += __shfl_xor_sync(0xffffffffu, rs, 2);
            l_i[hh] = l_i[hh] * corr + rs;
            #pragma unroll
            for (int nt = 0; nt < 8; nt++) {
                o[nt][hh * 2]     *= corr;
                o[nt][hh * 2 + 1] *= corr;
            }
        }

        // ---- O += P @ V ----
        #pragma unroll
        for (int jj = 0; jj < 4; jj++) {
            uint32_t pa0 = packh2(s[2 * jj][0],     s[2 * jj][1]);
            uint32_t pa1 = packh2(s[2 * jj][2],     s[2 * jj][3]);
            uint32_t pa2 = packh2(s[2 * jj + 1][0], s[2 * jj + 1][1]);
            uint32_t pa3 = packh2(s[2 * jj + 1][2], s[2 * jj + 1][3]);
            #pragma unroll
            for (int p = 0; p < 4; p++) {
                uint32_t b0, b1, b2, b3;
                ldsm_x4_t(b0, b1, b2, b3, uVb + jj * 16 * 144 + p * 32 + offA);
                mma_f16(o[2 * p],     pa0, pa1, pa2, pa3, b0, b1);
                mma_f16(o[2 * p + 1], pa0, pa1, pa2, pa3, b2, b3);
            }
        }
    }

    // ---- epilogue: normalize + scatter to original row indices ----
    #pragma unroll
    for (int hh = 0; hh < 2; hh++) {
        if (!(hh ? valid1 : valid0)) continue;
        const int qrow = hh ? qi1 : qi0;
        float inv = 1.f / l_i[hh];
        __half* dstp = &g_oh[(size_t)(b * LTOT + qrow) * INNER + h * DHEAD];
        #pragma unroll
        for (int nt = 0; nt < 8; nt++) {
            int d0 = nt * 8 + 2 * qd;
            *(__half2*)&dstp[d0] =
                __floats2half2_rn(o[nt][hh * 2] * inv, o[nt][hh * 2 + 1] * inv);
        }
    }

    // Fallback: if no idle CTAs exist, last CTA patches everything.
    if (nidle == 0 && blockIdx.x == QTILES - 1) {
        __syncthreads();
        patch_tiles(b, h, bh, 0, 1);
    }
}

// ---------------------------------------------------------------------------
// kernel_launch
// ---------------------------------------------------------------------------
extern "C" void kernel_launch(void* const* d_in, const int* in_sizes, int n_in,
                              void* d_out, int out_size) {
    const float* nodes = (const float*)d_in[0];
    const float* edges = (const float*)d_in[1];
    const unsigned char* mask_raw = (const unsigned char*)d_in[2];
    const float* Wq  = (const float*)d_in[3];
    const float* bq  = (const float*)d_in[4];
    const float* Wk  = (const float*)d_in[5];
    const float* bk  = (const float*)d_in[6];
    const float* Wv  = (const float*)d_in[7];
    const float* bv  = (const float*)d_in[8];
    const float* Weq = (const float*)d_in[9];
    const float* beq = (const float*)d_in[10];
    const float* Wek = (const float*)d_in[11];
    const float* bek = (const float*)d_in[12];
    const float* Wev = (const float*)d_in[13];
    const float* bev = (const float*)d_in[14];
    const float* Wo  = (const float*)d_in[15];
    const float* bo  = (const float*)d_in[16];
    const float* Weo = (const float*)d_in[17];
    const float* beo = (const float*)d_in[18];
    float* out = (float*)d_out;

    void *qp, *kp, *vp;
    cudaGetSymbolAddress(&qp, g_qh);
    cudaGetSymbolAddress(&kp, g_kh);
    cudaGetSymbolAddress(&vp, g_vh);

    mask_kernel<<<BSZ, 256>>>(mask_raw);

    // All six QKV projections in one launch
    qkv_kernel<<<1152, 256>>>(
        nodes, edges, Wq, Wk, Wv, bq, bk, bv,
        Weq, Wek, Wev, beq, bek, bev,
        (__half*)qp, (__half*)kp, (__half*)vp, SCALE * LOG2E);

    // Partial V sums per (b,h)
    vmean_kernel<<<BSZ * HEADS * NCH, 256>>>();

    // Flash attention (Br=64, 128 threads) + patch in idle CTAs
    cudaFuncSetAttribute(attn_f16_kernel,
                         cudaFuncAttributeMaxDynamicSharedMemorySize, ATTN_SMEM_BYTES);
    attn_f16_kernel<<<dim3(QTILES, BSZ * HEADS), 128, ATTN_SMEM_BYTES>>>();

    // Both output projections in one launch
    outproj_kernel<<<160, 256>>>(Wo, bo, Weo, beo, out);
}